// round 12
// baseline (speedup 1.0000x reference)
#include <cuda_runtime.h>
#include <cuda_fp16.h>
#include <cstdint>

#define D 512
#define KDIM 1024
#define NODES_MAX 50176          // multiple of 128, >= 50048 (391*128)
#define BKT_CAP 128              // max degree capacity; Poisson(30) max ~60

// ---------------- device scratch (static, no allocation) ----------------
__device__ __half g_A[(size_t)NODES_MAX * KDIM];   // [node][k]: k<512 = mean, k>=512 = h
__device__ __half g_B[(size_t)D * KDIM];           // [out][k]:  k<512 = W_l, k>=512 = W_r
__device__ int    g_cnt[NODES_MAX];                // zero-init; gemm resets after agg consumed
__device__ int    g_bkt[(size_t)NODES_MAX * BKT_CAP];

// ---------------- LN -> h (fp16) + weight fp16 convert (fused) ----------------
__global__ void ln_kernel(const float* __restrict__ nf, const float* __restrict__ gamma,
                          const float* __restrict__ beta,
                          const float* __restrict__ Wl, const float* __restrict__ Wr, int n) {
    int i = blockIdx.x;
    int tid = threadIdx.x;                       // 128 threads

    if (i < 4096) {                              // weight convert: 4096*128 = D*KDIM
        int idx = i * 128 + tid;
        int r = idx >> 10, k = idx & 1023;
        float w = (k < D) ? Wl[r * D + k] : Wr[r * D + (k - D)];
        g_B[idx] = __float2half(w);
    }

    if (i >= n) return;
    float4 v = ((const float4*)(nf + (size_t)i * D))[tid];
    float s  = v.x + v.y + v.z + v.w;
    float ss = v.x * v.x + v.y * v.y + v.z * v.z + v.w * v.w;
#pragma unroll
    for (int o = 16; o > 0; o >>= 1) {
        s  += __shfl_xor_sync(0xffffffffu, s, o);
        ss += __shfl_xor_sync(0xffffffffu, ss, o);
    }
    __shared__ float red[8];
    int w = tid >> 5;
    if ((tid & 31) == 0) { red[w * 2] = s; red[w * 2 + 1] = ss; }
    __syncthreads();
    s  = red[0] + red[2] + red[4] + red[6];
    ss = red[1] + red[3] + red[5] + red[7];
    float mu   = s * (1.f / 512.f);
    float var  = ss * (1.f / 512.f) - mu * mu;
    float rstd = rsqrtf(var + 1e-5f);
    float4 g = ((const float4*)gamma)[tid];
    float4 b = ((const float4*)beta)[tid];
    float h0 = (v.x - mu) * rstd * g.x + b.x;
    float h1 = (v.y - mu) * rstd * g.y + b.y;
    float h2 = (v.z - mu) * rstd * g.z + b.z;
    float h3 = (v.w - mu) * rstd * g.w + b.w;
    __half2* dst = (__half2*)(g_A + (size_t)i * KDIM + D);
    dst[tid * 2]     = __floats2half2_rn(h0, h1);
    dst[tid * 2 + 1] = __floats2half2_rn(h2, h3);
}

// ---------------- bucket fill: histogram + grouped edge store ----------------
__global__ void fill_kernel(const int* __restrict__ eidx, int E) {
    int e = blockIdx.x * blockDim.x + threadIdx.x;
    if (e < E) {
        int d = eidx[E + e];                       // row 1 = dst
        int slot = atomicAdd(&g_cnt[d], 1);
        if (slot < BKT_CAP)
            g_bkt[(size_t)d * BKT_CAP + slot] = eidx[e];   // row 0 = src
    }
}

// ---------------- mean aggregation: 2 warps/node, 4-edge unroll (proven form) ----------------
__global__ void agg_kernel(int n) {
    int gw = (blockIdx.x * blockDim.x + threadIdx.x) >> 5;
    int lane = threadIdx.x & 31;
    int node = gw >> 1, part = gw & 1;
    if (node >= n) return;
    const int* bkt = g_bkt + (size_t)node * BKT_CAP;
    int deg = g_cnt[node];
    int m = deg < BKT_CAP ? deg : BKT_CAP;

    const size_t fOff = (size_t)D + part * 256 + lane * 8;
    float acc[8];
#pragma unroll
    for (int q = 0; q < 8; q++) acc[q] = 0.f;

    auto accum = [&](uint4 p) {
        const __half2* h = (const __half2*)&p;
#pragma unroll
        for (int q = 0; q < 4; q++) {
            float2 f = __half22float2(h[q]);
            acc[2 * q] += f.x; acc[2 * q + 1] += f.y;
        }
    };

    int j = 0;
    for (; j + 4 <= m; j += 4) {
        int s0 = bkt[j];
        int s1 = bkt[j + 1];
        int s2 = bkt[j + 2];
        int s3 = bkt[j + 3];
        uint4 p0 = *(const uint4*)(g_A + (size_t)s0 * KDIM + fOff);
        uint4 p1 = *(const uint4*)(g_A + (size_t)s1 * KDIM + fOff);
        uint4 p2 = *(const uint4*)(g_A + (size_t)s2 * KDIM + fOff);
        uint4 p3 = *(const uint4*)(g_A + (size_t)s3 * KDIM + fOff);
        accum(p0); accum(p1); accum(p2); accum(p3);
    }
    for (; j < m; ++j) {
        int s0 = bkt[j];
        accum(*(const uint4*)(g_A + (size_t)s0 * KDIM + fOff));
    }

    float inv = 1.f / (float)(deg > 0 ? deg : 1);
    uint4 o;
    __half2* q = (__half2*)&o;
#pragma unroll
    for (int k = 0; k < 4; k++)
        q[k] = __floats2half2_rn(acc[2 * k] * inv, acc[2 * k + 1] * inv);
    *(uint4*)(g_A + (size_t)node * KDIM + part * 256 + lane * 8) = o;
}

// ---------------- GEMM  C = A[M,1024] @ B[512,1024]^T + bias/relu/residual ----------------
// BM=128 BN=256 BK=64, warp tile 64x64 (2x4 warp grid), 3-stage cp.async, 1 sync/iter.
#define A_STG 16384              // 128 x 64 halves
#define B_STG 32768              // 256 x 64 halves
#define SM_TOT (3 * A_STG + 3 * B_STG)   // 147456
__global__ __launch_bounds__(256) void gemm_kernel(const float* __restrict__ nf,
                                                   const float* __restrict__ bl,
                                                   float* __restrict__ out, int n) {
    extern __shared__ __align__(16) unsigned char smem_raw[];
    const uint32_t smBase = (uint32_t)__cvta_generic_to_shared(smem_raw);
    const uint32_t asBase = smBase;                  // 3 x 16KB
    const uint32_t bsBase = smBase + 3 * A_STG;      // 3 x 32KB

    const int tid = threadIdx.x;

    // g_cnt reset for next replay (agg already consumed it; stream-ordered)
    {
        int flat = (blockIdx.y * gridDim.x + blockIdx.x) * 256 + tid;
        if (flat < NODES_MAX) g_cnt[flat] = 0;
    }

    const int lane = tid & 31, wid = tid >> 5;
    const int wr = wid & 1, wc = wid >> 1;          // 2 x 4 warp grid, warp tile 64x64
    const int rowBase = blockIdx.y * 128;
    const int colBase = blockIdx.x * 256;

    float acc[4][8][4];
#pragma unroll
    for (int mi = 0; mi < 4; mi++)
#pragma unroll
        for (int ni = 0; ni < 8; ni++)
#pragma unroll
            for (int q = 0; q < 4; q++) acc[mi][ni][q] = 0.f;

    auto load_stage = [&](int st, int kBase) {
#pragma unroll
        for (int i = 0; i < 4; i++) {                     // A: 128 rows x 8 chunks = 1024
            int cid = tid + i * 256;
            int r = cid >> 3, c = cid & 7;
            const __half* g = g_A + (size_t)(rowBase + r) * KDIM + kBase + c * 8;
            uint32_t s = asBase + st * A_STG + (r * 8 + (c ^ (r & 7))) * 16;
            asm volatile("cp.async.cg.shared.global [%0], [%1], 16;\n" ::"r"(s), "l"(g));
        }
#pragma unroll
        for (int i = 0; i < 8; i++) {                     // B: 256 rows x 8 chunks = 2048
            int cid = tid + i * 256;
            int r = cid >> 3, c = cid & 7;
            const __half* g = g_B + (size_t)(colBase + r) * KDIM + kBase + c * 8;
            uint32_t s = bsBase + st * B_STG + (r * 8 + (c ^ (r & 7))) * 16;
            asm volatile("cp.async.cg.shared.global [%0], [%1], 16;\n" ::"r"(s), "l"(g));
        }
    };

    load_stage(0, 0);
    asm volatile("cp.async.commit_group;\n");
    load_stage(1, 64);
    asm volatile("cp.async.commit_group;\n");

    for (int kt = 0; kt < 16; ++kt) {
        int cur = kt % 3;
        if (kt < 14) asm volatile("cp.async.wait_group 1;\n" ::: "memory");
        else         asm volatile("cp.async.wait_group 0;\n" ::: "memory");
        __syncthreads();                               // stage cur ready on all threads;
        if (kt + 2 < 16) {                             // all done computing stage (kt-1)%3
            load_stage((kt + 2) % 3, (kt + 2) * 64);   // (kt+2)%3 == (kt-1)%3: now safe to overwrite
            asm volatile("cp.async.commit_group;\n");
        }

        const uint32_t aB = asBase + cur * A_STG;
        const uint32_t bB = bsBase + cur * B_STG;
#pragma unroll
        for (int ks = 0; ks < 4; ++ks) {
            uint32_t a[4][4], b[8][2];
#pragma unroll
            for (int mi = 0; mi < 4; ++mi) {
                int r = wr * 64 + mi * 16 + (lane & 15);
                int ch = ks * 2 + (lane >> 4);
                uint32_t addr = aB + (r * 8 + (ch ^ (r & 7))) * 16;
                asm volatile("ldmatrix.sync.aligned.m8n8.x4.shared.b16 {%0,%1,%2,%3}, [%4];\n"
                             : "=r"(a[mi][0]), "=r"(a[mi][1]), "=r"(a[mi][2]), "=r"(a[mi][3])
                             : "r"(addr));
            }
#pragma unroll
            for (int ni = 0; ni < 8; ++ni) {
                int r = wc * 64 + ni * 8 + (lane & 7);
                int ch = ks * 2 + ((lane >> 3) & 1);
                uint32_t addr = bB + (r * 8 + (ch ^ (r & 7))) * 16;
                asm volatile("ldmatrix.sync.aligned.m8n8.x2.shared.b16 {%0,%1}, [%2];\n"
                             : "=r"(b[ni][0]), "=r"(b[ni][1])
                             : "r"(addr));
            }
#pragma unroll
            for (int mi = 0; mi < 4; mi++)
#pragma unroll
                for (int ni = 0; ni < 8; ni++)
                    asm volatile("mma.sync.aligned.m16n8k16.row.col.f32.f16.f16.f32 "
                                 "{%0,%1,%2,%3}, {%4,%5,%6,%7}, {%8,%9}, {%0,%1,%2,%3};\n"
                                 : "+f"(acc[mi][ni][0]), "+f"(acc[mi][ni][1]),
                                   "+f"(acc[mi][ni][2]), "+f"(acc[mi][ni][3])
                                 : "r"(a[mi][0]), "r"(a[mi][1]), "r"(a[mi][2]), "r"(a[mi][3]),
                                   "r"(b[ni][0]), "r"(b[ni][1]));
        }
    }

#pragma unroll
    for (int mi = 0; mi < 4; mi++)
#pragma unroll
        for (int ni = 0; ni < 8; ni++) {
            int row0 = rowBase + wr * 64 + mi * 16 + (lane >> 2);
            int col = colBase + wc * 64 + ni * 8 + (lane & 3) * 2;
            float b0 = __ldg(bl + col), b1 = __ldg(bl + col + 1);
            if (row0 < n) {
                const float2 r = *(const float2*)(nf + (size_t)row0 * D + col);
                float2 o;
                o.x = fmaxf(acc[mi][ni][0] + b0, 0.f) + r.x;
                o.y = fmaxf(acc[mi][ni][1] + b1, 0.f) + r.y;
                *(float2*)(out + (size_t)row0 * D + col) = o;
            }
            int row1 = row0 + 8;
            if (row1 < n) {
                const float2 r = *(const float2*)(nf + (size_t)row1 * D + col);
                float2 o;
                o.x = fmaxf(acc[mi][ni][2] + b0, 0.f) + r.x;
                o.y = fmaxf(acc[mi][ni][3] + b1, 0.f) + r.y;
                *(float2*)(out + (size_t)row1 * D + col) = o;
            }
        }
}

// ---------------- launch ----------------
extern "C" void kernel_launch(void* const* d_in, const int* in_sizes, int n_in,
                              void* d_out, int out_size) {
    const float* nf    = (const float*)d_in[0];
    const int*   eidx  = (const int*)d_in[1];
    const float* Wl    = (const float*)d_in[2];
    const float* bl    = (const float*)d_in[3];
    const float* Wr    = (const float*)d_in[4];
    const float* gamma = (const float*)d_in[5];
    const float* beta  = (const float*)d_in[6];
    float* out = (float*)d_out;

    int n = in_sizes[0] / D;      // 50000
    int E = in_sizes[1] / 2;      // 1500000

    cudaFuncSetAttribute(gemm_kernel, cudaFuncAttributeMaxDynamicSharedMemorySize, SM_TOT);

    ln_kernel<<<n, 128>>>(nf, gamma, beta, Wl, Wr, n);                   // 0 (LN + weights)
    fill_kernel<<<(E + 255) / 256, 256>>>(eidx, E);                      // 1
    agg_kernel<<<(n * 2 * 32 + 255) / 256, 256>>>(n);                    // 2
    gemm_kernel<<<dim3(2, (n + 127) / 128), 256, SM_TOT>>>(nf, bl, out, n); // 3  <- profiled
}

// round 13
// speedup vs baseline: 1.1424x; 1.1424x over previous
#include <cuda_runtime.h>
#include <cuda_fp16.h>
#include <cstdint>

#define D 512
#define KDIM 1024
#define NODES_MAX 50176          // multiple of 128, >= 50048 (391*128)
#define BKT_CAP 128              // max degree capacity; Poisson(30) max ~60

// ---------------- device scratch (static, no allocation) ----------------
__device__ __half g_A[(size_t)NODES_MAX * KDIM];   // [node][k]: k<512 = mean, k>=512 = h
__device__ __half g_B[(size_t)D * KDIM];           // [out][k]:  k<512 = W_l, k>=512 = W_r
__device__ int    g_cnt[NODES_MAX];                // zero-init; gemm resets after agg consumed
__device__ int    g_bkt[(size_t)NODES_MAX * BKT_CAP];

// ---- LN -> h (fp16) + weight fp16 convert + FULL edge bucketing (one kernel) ----
// Each block: LN for node i; warp 0 also deposits edges [i*epb, i*epb+epb) into buckets.
// The edge scatter's L2 latency hides under LN's DRAM streaming (R7-proven pattern).
__global__ void ln_fill_kernel(const float* __restrict__ nf, const float* __restrict__ gamma,
                               const float* __restrict__ beta, const int* __restrict__ eidx,
                               const float* __restrict__ Wl, const float* __restrict__ Wr,
                               int n, int E, int epb) {
    int i = blockIdx.x;
    int tid = threadIdx.x;                       // 128 threads

    if (i < 4096) {                              // weight convert: 4096*128 = D*KDIM
        int idx = i * 128 + tid;
        int r = idx >> 10, k = idx & 1023;
        float w = (k < D) ? Wl[r * D + k] : Wr[r * D + (k - D)];
        g_B[idx] = __float2half(w);
    }

    if (tid < epb) {                             // bucket fill slice (fire-and-forget)
        int e = i * epb + tid;
        if (e < E) {
            int d = eidx[E + e];                 // row 1 = dst
            int slot = atomicAdd(&g_cnt[d], 1);
            if (slot < BKT_CAP)
                g_bkt[(size_t)d * BKT_CAP + slot] = eidx[e];   // row 0 = src
        }
    }

    if (i >= n) return;
    float4 v = ((const float4*)(nf + (size_t)i * D))[tid];
    float s  = v.x + v.y + v.z + v.w;
    float ss = v.x * v.x + v.y * v.y + v.z * v.z + v.w * v.w;
#pragma unroll
    for (int o = 16; o > 0; o >>= 1) {
        s  += __shfl_xor_sync(0xffffffffu, s, o);
        ss += __shfl_xor_sync(0xffffffffu, ss, o);
    }
    __shared__ float red[8];
    int w = tid >> 5;
    if ((tid & 31) == 0) { red[w * 2] = s; red[w * 2 + 1] = ss; }
    __syncthreads();
    s  = red[0] + red[2] + red[4] + red[6];
    ss = red[1] + red[3] + red[5] + red[7];
    float mu   = s * (1.f / 512.f);
    float var  = ss * (1.f / 512.f) - mu * mu;
    float rstd = rsqrtf(var + 1e-5f);
    float4 g = ((const float4*)gamma)[tid];
    float4 b = ((const float4*)beta)[tid];
    float h0 = (v.x - mu) * rstd * g.x + b.x;
    float h1 = (v.y - mu) * rstd * g.y + b.y;
    float h2 = (v.z - mu) * rstd * g.z + b.z;
    float h3 = (v.w - mu) * rstd * g.w + b.w;
    __half2* dst = (__half2*)(g_A + (size_t)i * KDIM + D);
    dst[tid * 2]     = __floats2half2_rn(h0, h1);
    dst[tid * 2 + 1] = __floats2half2_rn(h2, h3);
}

// ---------------- mean aggregation: 2 warps/node, 4-edge unroll (proven form) ----------------
__global__ void agg_kernel(int n) {
    int gw = (blockIdx.x * blockDim.x + threadIdx.x) >> 5;
    int lane = threadIdx.x & 31;
    int node = gw >> 1, part = gw & 1;
    if (node >= n) return;
    const int* bkt = g_bkt + (size_t)node * BKT_CAP;
    int deg = g_cnt[node];
    int m = deg < BKT_CAP ? deg : BKT_CAP;

    const size_t fOff = (size_t)D + part * 256 + lane * 8;
    float acc[8];
#pragma unroll
    for (int q = 0; q < 8; q++) acc[q] = 0.f;

    auto accum = [&](uint4 p) {
        const __half2* h = (const __half2*)&p;
#pragma unroll
        for (int q = 0; q < 4; q++) {
            float2 f = __half22float2(h[q]);
            acc[2 * q] += f.x; acc[2 * q + 1] += f.y;
        }
    };

    int j = 0;
    for (; j + 4 <= m; j += 4) {
        int s0 = bkt[j];
        int s1 = bkt[j + 1];
        int s2 = bkt[j + 2];
        int s3 = bkt[j + 3];
        uint4 p0 = *(const uint4*)(g_A + (size_t)s0 * KDIM + fOff);
        uint4 p1 = *(const uint4*)(g_A + (size_t)s1 * KDIM + fOff);
        uint4 p2 = *(const uint4*)(g_A + (size_t)s2 * KDIM + fOff);
        uint4 p3 = *(const uint4*)(g_A + (size_t)s3 * KDIM + fOff);
        accum(p0); accum(p1); accum(p2); accum(p3);
    }
    for (; j < m; ++j) {
        int s0 = bkt[j];
        accum(*(const uint4*)(g_A + (size_t)s0 * KDIM + fOff));
    }

    float inv = 1.f / (float)(deg > 0 ? deg : 1);
    uint4 o;
    __half2* q = (__half2*)&o;
#pragma unroll
    for (int k = 0; k < 4; k++)
        q[k] = __floats2half2_rn(acc[2 * k] * inv, acc[2 * k + 1] * inv);
    *(uint4*)(g_A + (size_t)node * KDIM + part * 256 + lane * 8) = o;
}

// ---------------- GEMM  C = A[M,1024] @ B[512,1024]^T + bias/relu/residual ----------------
// BM=128 BN=128 BK=64, warp tile 64x32 (2x4), 2-stage cp.async; B loaded via ldmatrix.x4.
__global__ __launch_bounds__(256) void gemm_kernel(const float* __restrict__ nf,
                                                   const float* __restrict__ bl,
                                                   float* __restrict__ out, int n) {
    extern __shared__ __align__(16) unsigned char smem_raw[];
    const uint32_t smBase = (uint32_t)__cvta_generic_to_shared(smem_raw);
    const uint32_t asBase = smBase;
    const uint32_t bsBase = smBase + 32768;

    const int tid = threadIdx.x;

    // g_cnt reset for next replay (agg already consumed it; stream-ordered)
    {
        int flat = (blockIdx.y * gridDim.x + blockIdx.x) * 256 + tid;
        if (flat < NODES_MAX) g_cnt[flat] = 0;
    }

    const int lane = tid & 31, wid = tid >> 5;
    const int wr = wid & 1, wc = wid >> 1;          // 2 x 4 warp grid, warp tile 64x32
    const int rowBase = blockIdx.y * 128;
    const int colBase = blockIdx.x * 128;

    float acc[4][4][4];
#pragma unroll
    for (int mi = 0; mi < 4; mi++)
#pragma unroll
        for (int ni = 0; ni < 4; ni++)
#pragma unroll
            for (int q = 0; q < 4; q++) acc[mi][ni][q] = 0.f;

    auto load_stage = [&](int st, int kBase) {
#pragma unroll
        for (int i = 0; i < 4; i++) {                     // A: 128 rows x 8 chunks
            int cid = tid + i * 256;
            int r = cid >> 3, c = cid & 7;
            const __half* g = g_A + (size_t)(rowBase + r) * KDIM + kBase + c * 8;
            uint32_t s = asBase + st * 16384 + (r * 8 + (c ^ (r & 7))) * 16;
            asm volatile("cp.async.cg.shared.global [%0], [%1], 16;\n" ::"r"(s), "l"(g));
        }
#pragma unroll
        for (int i = 0; i < 4; i++) {                     // B: 128 rows x 8 chunks
            int cid = tid + i * 256;
            int r = cid >> 3, c = cid & 7;
            const __half* g = g_B + (size_t)(colBase + r) * KDIM + kBase + c * 8;
            uint32_t s = bsBase + st * 16384 + (r * 8 + (c ^ (r & 7))) * 16;
            asm volatile("cp.async.cg.shared.global [%0], [%1], 16;\n" ::"r"(s), "l"(g));
        }
    };

    load_stage(0, 0);
    asm volatile("cp.async.commit_group;\n");

    for (int kt = 0; kt < 16; ++kt) {
        int cur = kt & 1;
        if (kt + 1 < 16) load_stage((kt + 1) & 1, (kt + 1) * 64);
        asm volatile("cp.async.commit_group;\n");
        asm volatile("cp.async.wait_group 1;\n");
        __syncthreads();

        const uint32_t aB = asBase + cur * 16384;
        const uint32_t bB = bsBase + cur * 16384;
#pragma unroll
        for (int ks = 0; ks < 4; ++ks) {
            uint32_t a[4][4], b[4][2];
#pragma unroll
            for (int mi = 0; mi < 4; ++mi) {
                int r = wr * 64 + mi * 16 + (lane & 15);
                int ch = ks * 2 + (lane >> 4);
                uint32_t addr = aB + (r * 8 + (ch ^ (r & 7))) * 16;
                asm volatile("ldmatrix.sync.aligned.m8n8.x4.shared.b16 {%0,%1,%2,%3}, [%4];\n"
                             : "=r"(a[mi][0]), "=r"(a[mi][1]), "=r"(a[mi][2]), "=r"(a[mi][3])
                             : "r"(addr));
            }
            // B: two ldmatrix.x4, each covering (ni, ni+1) x (k-half 0, k-half 1)
#pragma unroll
            for (int nn = 0; nn < 2; ++nn) {
                int quad = lane >> 3;                      // 0..3 -> matrix index
                int niq = nn * 2 + (quad >> 1);
                int chq = ks * 2 + (quad & 1);
                int r = wc * 32 + niq * 8 + (lane & 7);
                uint32_t addr = bB + (r * 8 + (chq ^ (r & 7))) * 16;
                asm volatile("ldmatrix.sync.aligned.m8n8.x4.shared.b16 {%0,%1,%2,%3}, [%4];\n"
                             : "=r"(b[nn * 2][0]), "=r"(b[nn * 2][1]),
                               "=r"(b[nn * 2 + 1][0]), "=r"(b[nn * 2 + 1][1])
                             : "r"(addr));
            }
#pragma unroll
            for (int mi = 0; mi < 4; mi++)
#pragma unroll
                for (int ni = 0; ni < 4; ni++)
                    asm volatile("mma.sync.aligned.m16n8k16.row.col.f32.f16.f16.f32 "
                                 "{%0,%1,%2,%3}, {%4,%5,%6,%7}, {%8,%9}, {%0,%1,%2,%3};\n"
                                 : "+f"(acc[mi][ni][0]), "+f"(acc[mi][ni][1]),
                                   "+f"(acc[mi][ni][2]), "+f"(acc[mi][ni][3])
                                 : "r"(a[mi][0]), "r"(a[mi][1]), "r"(a[mi][2]), "r"(a[mi][3]),
                                   "r"(b[ni][0]), "r"(b[ni][1]));
        }
        __syncthreads();
    }

#pragma unroll
    for (int mi = 0; mi < 4; mi++)
#pragma unroll
        for (int ni = 0; ni < 4; ni++) {
            int row0 = rowBase + wr * 64 + mi * 16 + (lane >> 2);
            int col = colBase + wc * 32 + ni * 8 + (lane & 3) * 2;
            float b0 = __ldg(bl + col), b1 = __ldg(bl + col + 1);
            if (row0 < n) {
                const float2 r = *(const float2*)(nf + (size_t)row0 * D + col);
                float2 o;
                o.x = fmaxf(acc[mi][ni][0] + b0, 0.f) + r.x;
                o.y = fmaxf(acc[mi][ni][1] + b1, 0.f) + r.y;
                *(float2*)(out + (size_t)row0 * D + col) = o;
            }
            int row1 = row0 + 8;
            if (row1 < n) {
                const float2 r = *(const float2*)(nf + (size_t)row1 * D + col);
                float2 o;
                o.x = fmaxf(acc[mi][ni][2] + b0, 0.f) + r.x;
                o.y = fmaxf(acc[mi][ni][3] + b1, 0.f) + r.y;
                *(float2*)(out + (size_t)row1 * D + col) = o;
            }
        }
}

// ---------------- launch ----------------
extern "C" void kernel_launch(void* const* d_in, const int* in_sizes, int n_in,
                              void* d_out, int out_size) {
    const float* nf    = (const float*)d_in[0];
    const int*   eidx  = (const int*)d_in[1];
    const float* Wl    = (const float*)d_in[2];
    const float* bl    = (const float*)d_in[3];
    const float* Wr    = (const float*)d_in[4];
    const float* gamma = (const float*)d_in[5];
    const float* beta  = (const float*)d_in[6];
    float* out = (float*)d_out;

    int n = in_sizes[0] / D;      // 50000
    int E = in_sizes[1] / 2;      // 1500000
    int epb = (E + n - 1) / n;    // 30 edges per block

    cudaFuncSetAttribute(gemm_kernel, cudaFuncAttributeMaxDynamicSharedMemorySize, 65536);

    ln_fill_kernel<<<n, 128>>>(nf, gamma, beta, eidx, Wl, Wr, n, E, epb); // 0 (LN+weights+buckets)
    agg_kernel<<<(n * 2 * 32 + 255) / 256, 256>>>(n);                     // 1
    gemm_kernel<<<dim3(4, (n + 127) / 128), 256, 65536>>>(nf, bl, out, n); // 2 (resets g_cnt)
}

// round 14
// speedup vs baseline: 1.1461x; 1.0032x over previous
#include <cuda_runtime.h>
#include <cuda_fp16.h>
#include <cstdint>

#define D 512
#define KDIM 1024
#define NODES_MAX 50176          // multiple of 128, >= 50048 (391*128)
#define BKT_CAP 128              // max degree capacity; Poisson(30) max ~60

// ---------------- device scratch (static, no allocation) ----------------
__device__ __half g_A[(size_t)NODES_MAX * KDIM];   // [node][k]: k<512 = mean, k>=512 = h
__device__ __half g_B[(size_t)D * KDIM];           // [out][k]:  k<512 = W_l, k>=512 = W_r
__device__ int    g_cnt[NODES_MAX];                // zero-init; gemm resets after agg consumed
__device__ int    g_bkt[(size_t)NODES_MAX * BKT_CAP];

// ---------------- LN -> h (fp16), lean: no side jobs ----------------
__global__ void ln_kernel(const float* __restrict__ nf, const float* __restrict__ gamma,
                          const float* __restrict__ beta, int n) {
    int i = blockIdx.x;
    int tid = threadIdx.x;                       // 128 threads
    if (i >= n) return;
    float4 v = ((const float4*)(nf + (size_t)i * D))[tid];
    float s  = v.x + v.y + v.z + v.w;
    float ss = v.x * v.x + v.y * v.y + v.z * v.z + v.w * v.w;
#pragma unroll
    for (int o = 16; o > 0; o >>= 1) {
        s  += __shfl_xor_sync(0xffffffffu, s, o);
        ss += __shfl_xor_sync(0xffffffffu, ss, o);
    }
    __shared__ float red[8];
    int w = tid >> 5;
    if ((tid & 31) == 0) { red[w * 2] = s; red[w * 2 + 1] = ss; }
    __syncthreads();
    s  = red[0] + red[2] + red[4] + red[6];
    ss = red[1] + red[3] + red[5] + red[7];
    float mu   = s * (1.f / 512.f);
    float var  = ss * (1.f / 512.f) - mu * mu;
    float rstd = rsqrtf(var + 1e-5f);
    float4 g = ((const float4*)gamma)[tid];
    float4 b = ((const float4*)beta)[tid];
    float h0 = (v.x - mu) * rstd * g.x + b.x;
    float h1 = (v.y - mu) * rstd * g.y + b.y;
    float h2 = (v.z - mu) * rstd * g.z + b.z;
    float h3 = (v.w - mu) * rstd * g.w + b.w;
    __half2* dst = (__half2*)(g_A + (size_t)i * KDIM + D);
    dst[tid * 2]     = __floats2half2_rn(h0, h1);
    dst[tid * 2 + 1] = __floats2half2_rn(h2, h3);
}

// ---------------- bucket fill + weight fp16 convert (rides along on spare blocks) ----------------
__global__ void fill_kernel(const int* __restrict__ eidx,
                            const float* __restrict__ Wl, const float* __restrict__ Wr, int E) {
    int t = blockIdx.x * blockDim.x + threadIdx.x;

    if (t < D * KDIM) {                           // weight convert: 524288 elems
        int r = t >> 10, k = t & 1023;
        float w = (k < D) ? Wl[r * D + k] : Wr[r * D + (k - D)];
        g_B[t] = __float2half(w);
    }

    if (t < E) {
        int d = eidx[E + t];                       // row 1 = dst
        int slot = atomicAdd(&g_cnt[d], 1);
        if (slot < BKT_CAP)
            g_bkt[(size_t)d * BKT_CAP + slot] = eidx[t];   // row 0 = src
    }
}

// ---------------- mean aggregation: 2 warps/node, 4-edge unroll (proven form) ----------------
__global__ void agg_kernel(int n) {
    int gw = (blockIdx.x * blockDim.x + threadIdx.x) >> 5;
    int lane = threadIdx.x & 31;
    int node = gw >> 1, part = gw & 1;
    if (node >= n) return;
    const int* bkt = g_bkt + (size_t)node * BKT_CAP;
    int deg = g_cnt[node];
    int m = deg < BKT_CAP ? deg : BKT_CAP;

    const size_t fOff = (size_t)D + part * 256 + lane * 8;
    float acc[8];
#pragma unroll
    for (int q = 0; q < 8; q++) acc[q] = 0.f;

    auto accum = [&](uint4 p) {
        const __half2* h = (const __half2*)&p;
#pragma unroll
        for (int q = 0; q < 4; q++) {
            float2 f = __half22float2(h[q]);
            acc[2 * q] += f.x; acc[2 * q + 1] += f.y;
        }
    };

    int j = 0;
    for (; j + 4 <= m; j += 4) {
        int s0 = bkt[j];
        int s1 = bkt[j + 1];
        int s2 = bkt[j + 2];
        int s3 = bkt[j + 3];
        uint4 p0 = *(const uint4*)(g_A + (size_t)s0 * KDIM + fOff);
        uint4 p1 = *(const uint4*)(g_A + (size_t)s1 * KDIM + fOff);
        uint4 p2 = *(const uint4*)(g_A + (size_t)s2 * KDIM + fOff);
        uint4 p3 = *(const uint4*)(g_A + (size_t)s3 * KDIM + fOff);
        accum(p0); accum(p1); accum(p2); accum(p3);
    }
    for (; j < m; ++j) {
        int s0 = bkt[j];
        accum(*(const uint4*)(g_A + (size_t)s0 * KDIM + fOff));
    }

    float inv = 1.f / (float)(deg > 0 ? deg : 1);
    uint4 o;
    __half2* q = (__half2*)&o;
#pragma unroll
    for (int k = 0; k < 4; k++)
        q[k] = __floats2half2_rn(acc[2 * k] * inv, acc[2 * k + 1] * inv);
    *(uint4*)(g_A + (size_t)node * KDIM + part * 256 + lane * 8) = o;
}

// ---------------- GEMM  C = A[M,1024] @ B[512,1024]^T + bias/relu/residual ----------------
// BM=128 BN=128 BK=64, warp tile 64x32 (2x4), 2-stage cp.async; B via ldmatrix.x4 (R13-proven).
__global__ __launch_bounds__(256) void gemm_kernel(const float* __restrict__ nf,
                                                   const float* __restrict__ bl,
                                                   float* __restrict__ out, int n) {
    extern __shared__ __align__(16) unsigned char smem_raw[];
    const uint32_t smBase = (uint32_t)__cvta_generic_to_shared(smem_raw);
    const uint32_t asBase = smBase;
    const uint32_t bsBase = smBase + 32768;

    const int tid = threadIdx.x;

    // g_cnt reset for next replay (agg already consumed it; stream-ordered)
    {
        int flat = (blockIdx.y * gridDim.x + blockIdx.x) * 256 + tid;
        if (flat < NODES_MAX) g_cnt[flat] = 0;
    }

    const int lane = tid & 31, wid = tid >> 5;
    const int wr = wid & 1, wc = wid >> 1;          // 2 x 4 warp grid, warp tile 64x32
    const int rowBase = blockIdx.y * 128;
    const int colBase = blockIdx.x * 128;

    float acc[4][4][4];
#pragma unroll
    for (int mi = 0; mi < 4; mi++)
#pragma unroll
        for (int ni = 0; ni < 4; ni++)
#pragma unroll
            for (int q = 0; q < 4; q++) acc[mi][ni][q] = 0.f;

    auto load_stage = [&](int st, int kBase) {
#pragma unroll
        for (int i = 0; i < 4; i++) {                     // A: 128 rows x 8 chunks
            int cid = tid + i * 256;
            int r = cid >> 3, c = cid & 7;
            const __half* g = g_A + (size_t)(rowBase + r) * KDIM + kBase + c * 8;
            uint32_t s = asBase + st * 16384 + (r * 8 + (c ^ (r & 7))) * 16;
            asm volatile("cp.async.cg.shared.global [%0], [%1], 16;\n" ::"r"(s), "l"(g));
        }
#pragma unroll
        for (int i = 0; i < 4; i++) {                     // B: 128 rows x 8 chunks
            int cid = tid + i * 256;
            int r = cid >> 3, c = cid & 7;
            const __half* g = g_B + (size_t)(colBase + r) * KDIM + kBase + c * 8;
            uint32_t s = bsBase + st * 16384 + (r * 8 + (c ^ (r & 7))) * 16;
            asm volatile("cp.async.cg.shared.global [%0], [%1], 16;\n" ::"r"(s), "l"(g));
        }
    };

    load_stage(0, 0);
    asm volatile("cp.async.commit_group;\n");

    for (int kt = 0; kt < 16; ++kt) {
        int cur = kt & 1;
        if (kt + 1 < 16) load_stage((kt + 1) & 1, (kt + 1) * 64);
        asm volatile("cp.async.commit_group;\n");
        asm volatile("cp.async.wait_group 1;\n");
        __syncthreads();

        const uint32_t aB = asBase + cur * 16384;
        const uint32_t bB = bsBase + cur * 16384;
#pragma unroll
        for (int ks = 0; ks < 4; ++ks) {
            uint32_t a[4][4], b[4][2];
#pragma unroll
            for (int mi = 0; mi < 4; ++mi) {
                int r = wr * 64 + mi * 16 + (lane & 15);
                int ch = ks * 2 + (lane >> 4);
                uint32_t addr = aB + (r * 8 + (ch ^ (r & 7))) * 16;
                asm volatile("ldmatrix.sync.aligned.m8n8.x4.shared.b16 {%0,%1,%2,%3}, [%4];\n"
                             : "=r"(a[mi][0]), "=r"(a[mi][1]), "=r"(a[mi][2]), "=r"(a[mi][3])
                             : "r"(addr));
            }
            // B: two ldmatrix.x4, each covering (ni, ni+1) x (k-half 0, k-half 1)
#pragma unroll
            for (int nn = 0; nn < 2; ++nn) {
                int quad = lane >> 3;                      // 0..3 -> matrix index
                int niq = nn * 2 + (quad >> 1);
                int chq = ks * 2 + (quad & 1);
                int r = wc * 32 + niq * 8 + (lane & 7);
                uint32_t addr = bB + (r * 8 + (chq ^ (r & 7))) * 16;
                asm volatile("ldmatrix.sync.aligned.m8n8.x4.shared.b16 {%0,%1,%2,%3}, [%4];\n"
                             : "=r"(b[nn * 2][0]), "=r"(b[nn * 2][1]),
                               "=r"(b[nn * 2 + 1][0]), "=r"(b[nn * 2 + 1][1])
                             : "r"(addr));
            }
#pragma unroll
            for (int mi = 0; mi < 4; mi++)
#pragma unroll
                for (int ni = 0; ni < 4; ni++)
                    asm volatile("mma.sync.aligned.m16n8k16.row.col.f32.f16.f16.f32 "
                                 "{%0,%1,%2,%3}, {%4,%5,%6,%7}, {%8,%9}, {%0,%1,%2,%3};\n"
                                 : "+f"(acc[mi][ni][0]), "+f"(acc[mi][ni][1]),
                                   "+f"(acc[mi][ni][2]), "+f"(acc[mi][ni][3])
                                 : "r"(a[mi][0]), "r"(a[mi][1]), "r"(a[mi][2]), "r"(a[mi][3]),
                                   "r"(b[ni][0]), "r"(b[ni][1]));
        }
        __syncthreads();
    }

#pragma unroll
    for (int mi = 0; mi < 4; mi++)
#pragma unroll
        for (int ni = 0; ni < 4; ni++) {
            int row0 = rowBase + wr * 64 + mi * 16 + (lane >> 2);
            int col = colBase + wc * 32 + ni * 8 + (lane & 3) * 2;
            float b0 = __ldg(bl + col), b1 = __ldg(bl + col + 1);
            if (row0 < n) {
                const float2 r = *(const float2*)(nf + (size_t)row0 * D + col);
                float2 o;
                o.x = fmaxf(acc[mi][ni][0] + b0, 0.f) + r.x;
                o.y = fmaxf(acc[mi][ni][1] + b1, 0.f) + r.y;
                *(float2*)(out + (size_t)row0 * D + col) = o;
            }
            int row1 = row0 + 8;
            if (row1 < n) {
                const float2 r = *(const float2*)(nf + (size_t)row1 * D + col);
                float2 o;
                o.x = fmaxf(acc[mi][ni][2] + b0, 0.f) + r.x;
                o.y = fmaxf(acc[mi][ni][3] + b1, 0.f) + r.y;
                *(float2*)(out + (size_t)row1 * D + col) = o;
            }
        }
}

// ---------------- launch ----------------
extern "C" void kernel_launch(void* const* d_in, const int* in_sizes, int n_in,
                              void* d_out, int out_size) {
    const float* nf    = (const float*)d_in[0];
    const int*   eidx  = (const int*)d_in[1];
    const float* Wl    = (const float*)d_in[2];
    const float* bl    = (const float*)d_in[3];
    const float* Wr    = (const float*)d_in[4];
    const float* gamma = (const float*)d_in[5];
    const float* beta  = (const float*)d_in[6];
    float* out = (float*)d_out;

    int n = in_sizes[0] / D;      // 50000
    int E = in_sizes[1] / 2;      // 1500000

    cudaFuncSetAttribute(gemm_kernel, cudaFuncAttributeMaxDynamicSharedMemorySize, 65536);

    ln_kernel<<<n, 128>>>(nf, gamma, beta, n);                            // 0
    fill_kernel<<<(E + 255) / 256, 256>>>(eidx, Wl, Wr, E);               // 1 (+weights)
    agg_kernel<<<(n * 2 * 32 + 255) / 256, 256>>>(n);                     // 2
    gemm_kernel<<<dim3(4, (n + 127) / 128), 256, 65536>>>(nf, bl, out, n); // 3 <- profiled
}

// round 15
// speedup vs baseline: 1.1580x; 1.0104x over previous
#include <cuda_runtime.h>
#include <cuda_fp16.h>
#include <cstdint>

#define D 512
#define KDIM 1024
#define NODES_MAX 50176          // multiple of 128, >= 50048 (391*128)
#define BKT_CAP 128              // max degree capacity; Poisson(30) max ~60

// ---------------- device scratch (static, no allocation) ----------------
__device__ __half g_A[(size_t)NODES_MAX * KDIM];   // [node][k]: k<512 = mean, k>=512 = h
__device__ __half g_B[(size_t)D * KDIM];           // [out][k]:  k<512 = W_l, k>=512 = W_r
__device__ int    g_cnt[NODES_MAX];                // zero-init; gemm resets after agg consumed
__device__ int    g_bkt[(size_t)NODES_MAX * BKT_CAP];

// ---------------- LN -> h (fp16), lean ----------------
__global__ void ln_kernel(const float* __restrict__ nf, const float* __restrict__ gamma,
                          const float* __restrict__ beta, int n) {
    int i = blockIdx.x;
    int tid = threadIdx.x;                       // 128 threads
    if (i >= n) return;
    float4 v = ((const float4*)(nf + (size_t)i * D))[tid];
    float s  = v.x + v.y + v.z + v.w;
    float ss = v.x * v.x + v.y * v.y + v.z * v.z + v.w * v.w;
#pragma unroll
    for (int o = 16; o > 0; o >>= 1) {
        s  += __shfl_xor_sync(0xffffffffu, s, o);
        ss += __shfl_xor_sync(0xffffffffu, ss, o);
    }
    __shared__ float red[8];
    int w = tid >> 5;
    if ((tid & 31) == 0) { red[w * 2] = s; red[w * 2 + 1] = ss; }
    __syncthreads();
    s  = red[0] + red[2] + red[4] + red[6];
    ss = red[1] + red[3] + red[5] + red[7];
    float mu   = s * (1.f / 512.f);
    float var  = ss * (1.f / 512.f) - mu * mu;
    float rstd = rsqrtf(var + 1e-5f);
    float4 g = ((const float4*)gamma)[tid];
    float4 b = ((const float4*)beta)[tid];
    float h0 = (v.x - mu) * rstd * g.x + b.x;
    float h1 = (v.y - mu) * rstd * g.y + b.y;
    float h2 = (v.z - mu) * rstd * g.z + b.z;
    float h3 = (v.w - mu) * rstd * g.w + b.w;
    __half2* dst = (__half2*)(g_A + (size_t)i * KDIM + D);
    dst[tid * 2]     = __floats2half2_rn(h0, h1);
    dst[tid * 2 + 1] = __floats2half2_rn(h2, h3);
}

// ---------------- bucket fill + weight fp16 convert (side stream, ∥ ln) ----------------
__global__ void fill_kernel(const int* __restrict__ eidx,
                            const float* __restrict__ Wl, const float* __restrict__ Wr, int E) {
    int t = blockIdx.x * blockDim.x + threadIdx.x;

    if (t < D * KDIM) {                           // weight convert: 524288 elems
        int r = t >> 10, k = t & 1023;
        float w = (k < D) ? Wl[r * D + k] : Wr[r * D + (k - D)];
        g_B[t] = __float2half(w);
    }

    if (t < E) {
        int d = eidx[E + t];                       // row 1 = dst
        int slot = atomicAdd(&g_cnt[d], 1);
        if (slot < BKT_CAP)
            g_bkt[(size_t)d * BKT_CAP + slot] = eidx[t];   // row 0 = src
    }
}

// ---------------- mean aggregation: 2 warps/node, 4-edge unroll (proven form) ----------------
__global__ void agg_kernel(int n) {
    int gw = (blockIdx.x * blockDim.x + threadIdx.x) >> 5;
    int lane = threadIdx.x & 31;
    int node = gw >> 1, part = gw & 1;
    if (node >= n) return;
    const int* bkt = g_bkt + (size_t)node * BKT_CAP;
    int deg = g_cnt[node];
    int m = deg < BKT_CAP ? deg : BKT_CAP;

    const size_t fOff = (size_t)D + part * 256 + lane * 8;
    float acc[8];
#pragma unroll
    for (int q = 0; q < 8; q++) acc[q] = 0.f;

    auto accum = [&](uint4 p) {
        const __half2* h = (const __half2*)&p;
#pragma unroll
        for (int q = 0; q < 4; q++) {
            float2 f = __half22float2(h[q]);
            acc[2 * q] += f.x; acc[2 * q + 1] += f.y;
        }
    };

    int j = 0;
    for (; j + 4 <= m; j += 4) {
        int s0 = bkt[j];
        int s1 = bkt[j + 1];
        int s2 = bkt[j + 2];
        int s3 = bkt[j + 3];
        uint4 p0 = *(const uint4*)(g_A + (size_t)s0 * KDIM + fOff);
        uint4 p1 = *(const uint4*)(g_A + (size_t)s1 * KDIM + fOff);
        uint4 p2 = *(const uint4*)(g_A + (size_t)s2 * KDIM + fOff);
        uint4 p3 = *(const uint4*)(g_A + (size_t)s3 * KDIM + fOff);
        accum(p0); accum(p1); accum(p2); accum(p3);
    }
    for (; j < m; ++j) {
        int s0 = bkt[j];
        accum(*(const uint4*)(g_A + (size_t)s0 * KDIM + fOff));
    }

    float inv = 1.f / (float)(deg > 0 ? deg : 1);
    uint4 o;
    __half2* q = (__half2*)&o;
#pragma unroll
    for (int k = 0; k < 4; k++)
        q[k] = __floats2half2_rn(acc[2 * k] * inv, acc[2 * k + 1] * inv);
    *(uint4*)(g_A + (size_t)node * KDIM + part * 256 + lane * 8) = o;
}

// ---------------- GEMM  C = A[M,1024] @ B[512,1024]^T + bias/relu/residual ----------------
// BM=128 BN=128 BK=64, warp tile 64x32 (2x4), 2-stage cp.async (measured-best config).
__global__ __launch_bounds__(256) void gemm_kernel(const float* __restrict__ nf,
                                                   const float* __restrict__ bl,
                                                   float* __restrict__ out, int n) {
    extern __shared__ __align__(16) unsigned char smem_raw[];
    const uint32_t smBase = (uint32_t)__cvta_generic_to_shared(smem_raw);
    const uint32_t asBase = smBase;
    const uint32_t bsBase = smBase + 32768;

    const int tid = threadIdx.x;

    // g_cnt reset for next replay (agg already consumed it; stream-ordered)
    {
        int flat = (blockIdx.y * gridDim.x + blockIdx.x) * 256 + tid;
        if (flat < NODES_MAX) g_cnt[flat] = 0;
    }

    const int lane = tid & 31, wid = tid >> 5;
    const int wr = wid & 1, wc = wid >> 1;          // 2 x 4 warp grid, warp tile 64x32
    const int rowBase = blockIdx.y * 128;
    const int colBase = blockIdx.x * 128;

    float acc[4][4][4];
#pragma unroll
    for (int mi = 0; mi < 4; mi++)
#pragma unroll
        for (int ni = 0; ni < 4; ni++)
#pragma unroll
            for (int q = 0; q < 4; q++) acc[mi][ni][q] = 0.f;

    auto load_stage = [&](int st, int kBase) {
#pragma unroll
        for (int i = 0; i < 4; i++) {                     // A: 128 rows x 8 chunks
            int cid = tid + i * 256;
            int r = cid >> 3, c = cid & 7;
            const __half* g = g_A + (size_t)(rowBase + r) * KDIM + kBase + c * 8;
            uint32_t s = asBase + st * 16384 + (r * 8 + (c ^ (r & 7))) * 16;
            asm volatile("cp.async.cg.shared.global [%0], [%1], 16;\n" ::"r"(s), "l"(g));
        }
#pragma unroll
        for (int i = 0; i < 4; i++) {                     // B: 128 rows x 8 chunks
            int cid = tid + i * 256;
            int r = cid >> 3, c = cid & 7;
            const __half* g = g_B + (size_t)(colBase + r) * KDIM + kBase + c * 8;
            uint32_t s = bsBase + st * 16384 + (r * 8 + (c ^ (r & 7))) * 16;
            asm volatile("cp.async.cg.shared.global [%0], [%1], 16;\n" ::"r"(s), "l"(g));
        }
    };

    load_stage(0, 0);
    asm volatile("cp.async.commit_group;\n");

    for (int kt = 0; kt < 16; ++kt) {
        int cur = kt & 1;
        if (kt + 1 < 16) load_stage((kt + 1) & 1, (kt + 1) * 64);
        asm volatile("cp.async.commit_group;\n");
        asm volatile("cp.async.wait_group 1;\n");
        __syncthreads();

        const uint32_t aB = asBase + cur * 16384;
        const uint32_t bB = bsBase + cur * 16384;
#pragma unroll
        for (int ks = 0; ks < 4; ++ks) {
            uint32_t a[4][4], b[4][2];
#pragma unroll
            for (int mi = 0; mi < 4; ++mi) {
                int r = wr * 64 + mi * 16 + (lane & 15);
                int ch = ks * 2 + (lane >> 4);
                uint32_t addr = aB + (r * 8 + (ch ^ (r & 7))) * 16;
                asm volatile("ldmatrix.sync.aligned.m8n8.x4.shared.b16 {%0,%1,%2,%3}, [%4];\n"
                             : "=r"(a[mi][0]), "=r"(a[mi][1]), "=r"(a[mi][2]), "=r"(a[mi][3])
                             : "r"(addr));
            }
#pragma unroll
            for (int nn = 0; nn < 2; ++nn) {
                int quad = lane >> 3;
                int niq = nn * 2 + (quad >> 1);
                int chq = ks * 2 + (quad & 1);
                int r = wc * 32 + niq * 8 + (lane & 7);
                uint32_t addr = bB + (r * 8 + (chq ^ (r & 7))) * 16;
                asm volatile("ldmatrix.sync.aligned.m8n8.x4.shared.b16 {%0,%1,%2,%3}, [%4];\n"
                             : "=r"(b[nn * 2][0]), "=r"(b[nn * 2][1]),
                               "=r"(b[nn * 2 + 1][0]), "=r"(b[nn * 2 + 1][1])
                             : "r"(addr));
            }
#pragma unroll
            for (int mi = 0; mi < 4; mi++)
#pragma unroll
                for (int ni = 0; ni < 4; ni++)
                    asm volatile("mma.sync.aligned.m16n8k16.row.col.f32.f16.f16.f32 "
                                 "{%0,%1,%2,%3}, {%4,%5,%6,%7}, {%8,%9}, {%0,%1,%2,%3};\n"
                                 : "+f"(acc[mi][ni][0]), "+f"(acc[mi][ni][1]),
                                   "+f"(acc[mi][ni][2]), "+f"(acc[mi][ni][3])
                                 : "r"(a[mi][0]), "r"(a[mi][1]), "r"(a[mi][2]), "r"(a[mi][3]),
                                   "r"(b[ni][0]), "r"(b[ni][1]));
        }
        __syncthreads();
    }

#pragma unroll
    for (int mi = 0; mi < 4; mi++)
#pragma unroll
        for (int ni = 0; ni < 4; ni++) {
            int row0 = rowBase + wr * 64 + mi * 16 + (lane >> 2);
            int col = colBase + wc * 32 + ni * 8 + (lane & 3) * 2;
            float b0 = __ldg(bl + col), b1 = __ldg(bl + col + 1);
            if (row0 < n) {
                const float2 r = *(const float2*)(nf + (size_t)row0 * D + col);
                float2 o;
                o.x = fmaxf(acc[mi][ni][0] + b0, 0.f) + r.x;
                o.y = fmaxf(acc[mi][ni][1] + b1, 0.f) + r.y;
                *(float2*)(out + (size_t)row0 * D + col) = o;
            }
            int row1 = row0 + 8;
            if (row1 < n) {
                const float2 r = *(const float2*)(nf + (size_t)row1 * D + col);
                float2 o;
                o.x = fmaxf(acc[mi][ni][2] + b0, 0.f) + r.x;
                o.y = fmaxf(acc[mi][ni][3] + b1, 0.f) + r.y;
                *(float2*)(out + (size_t)row1 * D + col) = o;
            }
        }
}

// ---------------- launch: ln ∥ fill fork-join (R10-proven stream mechanics) ----------------
extern "C" void kernel_launch(void* const* d_in, const int* in_sizes, int n_in,
                              void* d_out, int out_size) {
    const float* nf    = (const float*)d_in[0];
    const int*   eidx  = (const int*)d_in[1];
    const float* Wl    = (const float*)d_in[2];
    const float* bl    = (const float*)d_in[3];
    const float* Wr    = (const float*)d_in[4];
    const float* gamma = (const float*)d_in[5];
    const float* beta  = (const float*)d_in[6];
    float* out = (float*)d_out;

    int n = in_sizes[0] / D;      // 50000
    int E = in_sizes[1] / 2;      // 1500000

    static cudaStream_t s2 = nullptr;
    static cudaEvent_t evFork = nullptr, evJoin = nullptr;
    static bool init = false;
    if (!init) {
        cudaStreamCreateWithFlags(&s2, cudaStreamNonBlocking);
        cudaEventCreateWithFlags(&evFork, cudaEventDisableTiming);
        cudaEventCreateWithFlags(&evJoin, cudaEventDisableTiming);
        cudaFuncSetAttribute(gemm_kernel, cudaFuncAttributeMaxDynamicSharedMemorySize, 65536);
        init = true;
    }

    // fork at the very top: fill (atomic-bound) runs beside ln (DRAM-bound)
    cudaEventRecord(evFork, 0);
    cudaStreamWaitEvent(s2, evFork, 0);
    fill_kernel<<<(E + 255) / 256, 256, 0, s2>>>(eidx, Wl, Wr, E);
    cudaEventRecord(evJoin, s2);

    ln_kernel<<<n, 128>>>(nf, gamma, beta, n);

    cudaStreamWaitEvent(0, evJoin, 0);          // join: agg needs both
    agg_kernel<<<(n * 2 * 32 + 255) / 256, 256>>>(n);
    gemm_kernel<<<dim3(4, (n + 127) / 128), 256, 65536>>>(nf, bl, out, n);
}